// round 13
// baseline (speedup 1.0000x reference)
#include <cuda_runtime.h>
#include <cuda_bf16.h>
#include <cuda_fp8.h>
#include <math.h>
#include <stdint.h>

#define DIM 2048
#define T_LEN 2048
#define NHEAD 16
#define HDIM 128
#define ATTN_SCALE 0.12f

// ---------------- scratch ----------------
__device__ float g_qkv[T_LEN * 3 * DIM];
__device__ __nv_bfloat16 g_whi[4 * DIM * DIM];
__device__ __nv_bfloat16 g_xhi[T_LEN * DIM];
__device__ __nv_bfloat16 g_yhi[T_LEN * DIM];
__device__ uint8_t g_w8[4 * DIM * 2 * DIM];   // [row][2K] : [lo|hi] per 64B k-chunk group
__device__ uint8_t g_x8[T_LEN * 2 * DIM];     // [row][2K] : [hi|lo]
__device__ uint8_t g_y8[T_LEN * 2 * DIM];     // [row][2K] : [hi|lo]
__device__ __nv_bfloat16 g_qh[NHEAD * T_LEN * HDIM];
__device__ __nv_bfloat16 g_ql[NHEAD * T_LEN * HDIM];
__device__ __nv_bfloat16 g_kh[NHEAD * T_LEN * HDIM];
__device__ __nv_bfloat16 g_kl[NHEAD * T_LEN * HDIM];
__device__ __nv_bfloat16 g_vh[NHEAD * T_LEN * HDIM];
__device__ __nv_bfloat16 g_vl[NHEAD * T_LEN * HDIM];

// ---------------- PTX helpers (portable sm_80/89+) ----------------
__device__ __forceinline__ uint32_t smem_to_u32(const void* p) {
    uint32_t a;
    asm("{ .reg .u64 t; cvta.to.shared.u64 t, %1; cvt.u32.u64 %0, t; }" : "=r"(a) : "l"(p));
    return a;
}
__device__ __forceinline__ void cp16(uint32_t dst, const void* src) {
    asm volatile("cp.async.cg.shared.global [%0], [%1], 16;" :: "r"(dst), "l"(src) : "memory");
}
__device__ __forceinline__ void ldsm4(uint32_t* r, uint32_t a) {
    asm volatile("ldmatrix.sync.aligned.m8n8.x4.shared.b16 {%0,%1,%2,%3}, [%4];"
        : "=r"(r[0]), "=r"(r[1]), "=r"(r[2]), "=r"(r[3]) : "r"(a));
}
__device__ __forceinline__ void ldsm2(uint32_t* r, uint32_t a) {
    asm volatile("ldmatrix.sync.aligned.m8n8.x2.shared.b16 {%0,%1}, [%2];"
        : "=r"(r[0]), "=r"(r[1]) : "r"(a));
}
__device__ __forceinline__ void ldsm2t(uint32_t* r, uint32_t a) {
    asm volatile("ldmatrix.sync.aligned.m8n8.x2.trans.shared.b16 {%0,%1}, [%2];"
        : "=r"(r[0]), "=r"(r[1]) : "r"(a));
}
__device__ __forceinline__ void mma16816(float* d, const uint32_t* a, const uint32_t* b) {
    asm volatile("mma.sync.aligned.m16n8k16.row.col.f32.bf16.bf16.f32 "
        "{%0,%1,%2,%3}, {%4,%5,%6,%7}, {%8,%9}, {%0,%1,%2,%3};"
        : "+f"(d[0]), "+f"(d[1]), "+f"(d[2]), "+f"(d[3])
        : "r"(a[0]), "r"(a[1]), "r"(a[2]), "r"(a[3]), "r"(b[0]), "r"(b[1]));
}
// fp8 e4m3 MMA, k=32, zero C (partial product)
__device__ __forceinline__ void mma8_zero(float* d, const uint32_t* a, const uint32_t* b) {
    asm volatile("mma.sync.aligned.m16n8k32.row.col.f32.e4m3.e4m3.f32 "
        "{%0,%1,%2,%3}, {%4,%5,%6,%7}, {%8,%9}, {%10,%11,%12,%13};"
        : "=f"(d[0]), "=f"(d[1]), "=f"(d[2]), "=f"(d[3])
        : "r"(a[0]), "r"(a[1]), "r"(a[2]), "r"(a[3]), "r"(b[0]), "r"(b[1]),
          "f"(0.0f), "f"(0.0f), "f"(0.0f), "f"(0.0f));
}

// fast e^x for x <= 0 (FMA pipe only)
__device__ __forceinline__ float fexp(float x) {
    float t = fmaxf(x * 1.4426950408889634f, -80.0f);
    float z = t + 12582912.0f;
    float f = t - (z - 12582912.0f);
    int  i = __float_as_int(z) - 0x4B400000;
    float p = 1.3333558146e-3f;
    p = fmaf(p, f, 9.6181291076e-3f);
    p = fmaf(p, f, 5.5504108664e-2f);
    p = fmaf(p, f, 2.4022650696e-1f);
    p = fmaf(p, f, 6.9314718056e-1f);
    p = fmaf(p, f, 1.0f);
    return __int_as_float(__float_as_int(p) + (i << 23));
}

// ---------------- split: fp32 -> bf16 hi + fp8 (hi,lo) pair ----------------
// One thread per (row, 32-k chunk). f8 layout per chunk: 64 bytes = [first|second]
// first/second = (swap ? lo,hi : hi,lo). hi8 = e4m3(v*s_hi), lo8 = e4m3((v-bf16(v))*s_lo).
__global__ __launch_bounds__(256) void split_kernel(
    const float* __restrict__ src, __nv_bfloat16* __restrict__ hi,
    uint8_t* __restrict__ f8, int K, float s_hi, float s_lo, int swap)
{
    int idx = blockIdx.x * 256 + threadIdx.x;
    int cpr = K >> 5;
    int row = idx / cpr, c = idx % cpr;
    const float4* s4 = (const float4*)(src + (size_t)row * K + c * 32);
    float v[32], lo[32];
    #pragma unroll
    for (int i = 0; i < 8; i++) {
        float4 t = s4[i];
        v[4*i] = t.x; v[4*i+1] = t.y; v[4*i+2] = t.z; v[4*i+3] = t.w;
    }
    uint32_t hb[16];
    #pragma unroll
    for (int i = 0; i < 32; i++) {
        __nv_bfloat16 h = __float2bfloat16(v[i]);
        lo[i] = v[i] - __bfloat162float(h);
        uint32_t u = (uint32_t)__bfloat16_as_ushort(h);
        if (i & 1) hb[i >> 1] |= u << 16; else hb[i >> 1] = u;
    }
    uint4* hdst = (uint4*)(hi + (size_t)row * K + c * 32);
    #pragma unroll
    for (int i = 0; i < 4; i++)
        hdst[i] = make_uint4(hb[4*i], hb[4*i+1], hb[4*i+2], hb[4*i+3]);

    uint32_t ph[8], pl[8];
    #pragma unroll
    for (int i = 0; i < 16; i++) {
        float2 a = make_float2(v[2*i] * s_hi, v[2*i+1] * s_hi);
        float2 b = make_float2(lo[2*i] * s_lo, lo[2*i+1] * s_lo);
        uint32_t ha = (uint32_t)__nv_cvt_float2_to_fp8x2(a, __NV_SATFINITE, __NV_E4M3);
        uint32_t la = (uint32_t)__nv_cvt_float2_to_fp8x2(b, __NV_SATFINITE, __NV_E4M3);
        if (i & 1) { ph[i >> 1] |= ha << 16; pl[i >> 1] |= la << 16; }
        else       { ph[i >> 1]  = ha;       pl[i >> 1]  = la; }
    }
    uint8_t* base = f8 + (size_t)row * (2 * K) + c * 64;
    uint4* hi_p = (uint4*)(base + (swap ? 32 : 0));
    uint4* lo_p = (uint4*)(base + (swap ? 0 : 32));
    hi_p[0] = make_uint4(ph[0], ph[1], ph[2], ph[3]);
    hi_p[1] = make_uint4(ph[4], ph[5], ph[6], ph[7]);
    lo_p[0] = make_uint4(pl[0], pl[1], pl[2], pl[3]);
    lo_p[1] = make_uint4(pl[4], pl[5], pl[6], pl[7]);
}

// ---------------- bf16-hi + fp8-cross GEMM: C[M,N] = A[M,K] * B[N,K]^T ----------------
// CTA 128x128, 8 warps (64x32 warp tiles), K-chunk 32, double buffer, 2 CTAs/SM.
#define GKC 32
#define ROWB 80
#define AHI_OFF 0
#define BHI_OFF 10240
#define A8_OFF 20480
#define B8_OFF 30720
#define STAGE_BYTES 40960
#define GEMM_SMEM (2 * STAGE_BYTES)
#define CROSS_SCALE 6.103515625e-05f   // 2^-14

__global__ __launch_bounds__(256, 2) void gemm_hif8(
    const __nv_bfloat16* __restrict__ Ahi, const uint8_t* __restrict__ A8,
    const __nv_bfloat16* __restrict__ Bhi, const uint8_t* __restrict__ B8,
    float* __restrict__ C, int M, int N, int K)
{
    extern __shared__ char smc[];
    uint32_t smem_base = smem_to_u32(smc);
    int tid = threadIdx.x, wid = tid >> 5, lane = tid & 31;
    int m0 = blockIdx.y * 128, n0 = blockIdx.x * 128;
    int wy = wid & 1, wx = wid >> 1;
    int mb = wy * 64, nb = wx * 32;

    uint32_t arow  = (uint32_t)((lane & 15) * ROWB + ((lane >> 4) & 1) * 16);
    uint32_t brow4 = (uint32_t)(((lane & 7) + ((lane >> 4) & 1) * 8) * ROWB + ((lane >> 3) & 1) * 16);

    float acc[4][4][4];
    #pragma unroll
    for (int i = 0; i < 4; i++)
        #pragma unroll
        for (int j = 0; j < 4; j++)
            #pragma unroll
            for (int u = 0; u < 4; u++) acc[i][j][u] = 0.0f;

    auto fill_async = [&](int s, int k0) {
        uint32_t sb = smem_base + s * STAGE_BYTES;
        // each array: 128 rows x 64B = 512 cp16; 4 arrays = 2048 cp16 / 256 thr = 8
        #pragma unroll
        for (int rep = 0; rep < 2; rep++) {
            int i = tid + rep * 256;
            int row = i >> 2, seg = i & 3;
            uint32_t doff = (uint32_t)(row * ROWB + seg * 16);
            cp16(sb + AHI_OFF + doff, Ahi + (size_t)(m0 + row) * K + k0 + seg * 8);
            cp16(sb + BHI_OFF + doff, Bhi + (size_t)(n0 + row) * K + k0 + seg * 8);
            cp16(sb + A8_OFF + doff, A8 + (size_t)(m0 + row) * (2 * K) + k0 * 2 + seg * 16);
            cp16(sb + B8_OFF + doff, B8 + (size_t)(n0 + row) * (2 * K) + k0 * 2 + seg * 16);
        }
    };

    const int nchunks = K / GKC;
    fill_async(0, 0);
    asm volatile("cp.async.commit_group;" ::: "memory");
    asm volatile("cp.async.wait_group 0;" ::: "memory");
    __syncthreads();

    for (int c = 0; c < nchunks; c++) {
        if (c + 1 < nchunks) fill_async((c + 1) & 1, (c + 1) * GKC);
        asm volatile("cp.async.commit_group;" ::: "memory");

        uint32_t sb = smem_base + (c & 1) * STAGE_BYTES;

        // ---- bf16 hi*hi: 2 k-steps of 16 ----
        #pragma unroll
        for (int ks = 0; ks < 2; ks++) {
            uint32_t ah[4][4];
            #pragma unroll
            for (int mi = 0; mi < 4; mi++)
                ldsm4(ah[mi], sb + AHI_OFF + (uint32_t)((mb + mi * 16) * ROWB + ks * 32) + arow);
            #pragma unroll
            for (int np = 0; np < 2; np++) {
                uint32_t bh[4];
                ldsm4(bh, sb + BHI_OFF + (uint32_t)((nb + np * 16) * ROWB + ks * 32) + brow4);
                #pragma unroll
                for (int half = 0; half < 2; half++) {
                    int ni = 2 * np + half;
                    #pragma unroll
                    for (int mi = 0; mi < 4; mi++)
                        mma16816(acc[mi][ni], ah[mi], bh + 2 * half);
                }
            }
        }

        // ---- fp8 cross: stacked [Ahi|Alo*2^9] x [Blo*2^14|Bhi*2^5], 2 k32 halves ----
        #pragma unroll
        for (int s8 = 0; s8 < 2; s8++) {
            uint32_t b8r[2][4];
            #pragma unroll
            for (int np = 0; np < 2; np++)
                ldsm4(b8r[np], sb + B8_OFF + (uint32_t)((nb + np * 16) * ROWB + s8 * 32) + brow4);
            #pragma unroll
            for (int mi = 0; mi < 4; mi++) {
                uint32_t a8[4];
                ldsm4(a8, sb + A8_OFF + (uint32_t)((mb + mi * 16) * ROWB + s8 * 32) + arow);
                #pragma unroll
                for (int ni = 0; ni < 4; ni++) {
                    float tmp[4];
                    mma8_zero(tmp, a8, &b8r[ni >> 1][(ni & 1) * 2]);
                    #pragma unroll
                    for (int u = 0; u < 4; u++)
                        acc[mi][ni][u] = fmaf(tmp[u], CROSS_SCALE, acc[mi][ni][u]);
                }
            }
        }

        asm volatile("cp.async.wait_group 0;" ::: "memory");
        __syncthreads();
    }

    int r0 = lane >> 2, c2 = (lane & 3) * 2;
    #pragma unroll
    for (int mi = 0; mi < 4; mi++) {
        int rowa = m0 + mb + mi * 16 + r0;
        #pragma unroll
        for (int ni = 0; ni < 4; ni++) {
            int col = n0 + nb + ni * 8 + c2;
            *(float2*)(C + (size_t)rowa * N + col) = make_float2(acc[mi][ni][0], acc[mi][ni][1]);
            *(float2*)(C + (size_t)(rowa + 8) * N + col) = make_float2(acc[mi][ni][2], acc[mi][ni][3]);
        }
    }
}

// ---------------- RMSNorm + RoPE + v-mix -> bf16 hi/lo (attention operands) ----------------
__global__ __launch_bounds__(128) void fuse_kernel(
    const float* __restrict__ qkv, const float* __restrict__ ve,
    const float* __restrict__ lambdas,
    __nv_bfloat16* __restrict__ Qh, __nv_bfloat16* __restrict__ Ql,
    __nv_bfloat16* __restrict__ Kh, __nv_bfloat16* __restrict__ Kl,
    __nv_bfloat16* __restrict__ Vh, __nv_bfloat16* __restrict__ Vl)
{
    int t = blockIdx.x, h = blockIdx.y, d = threadIdx.x;
    size_t base = (size_t)t * (3*DIM) + h * HDIM + d;
    float q = qkv[base];
    float k = qkv[base + DIM];
    float v = qkv[base + 2*DIM];

    __shared__ float red[3][4];
    __shared__ float qn_s[128], kn_s[128];
    float sq = q*q, sk = k*k, sv = v*v;
    #pragma unroll
    for (int off = 16; off > 0; off >>= 1) {
        sq += __shfl_xor_sync(0xffffffffu, sq, off);
        sk += __shfl_xor_sync(0xffffffffu, sk, off);
        sv += __shfl_xor_sync(0xffffffffu, sv, off);
    }
    int warp = d >> 5, lane = d & 31;
    if (lane == 0) { red[0][warp] = sq; red[1][warp] = sk; red[2][warp] = sv; }
    __syncthreads();
    sq = red[0][0]+red[0][1]+red[0][2]+red[0][3];
    sk = red[1][0]+red[1][1]+red[1][2]+red[1][3];
    sv = red[2][0]+red[2][1]+red[2][2]+red[2][3];
    float rq = rsqrtf(sq * (1.0f/128.0f) + 1e-6f);
    float rk = rsqrtf(sk * (1.0f/128.0f) + 1e-6f);
    float rv = rsqrtf(sv * (1.0f/128.0f) + 1e-6f);
    float qn = q * rq, kn = k * rk, vn = v * rv;
    qn_s[d] = qn; kn_s[d] = kn;
    __syncthreads();

    int j = (d < 64) ? d : (d - 64);
    float f = (j < 32) ? exp2f(-10.0f * (float)j / 31.0f) : 0.0f;
    float th = (float)t * f;
    float sn, cs;
    sincosf(th, &sn, &cs);
    float oq, ok;
    if (d < 64) {
        oq =  qn * cs + qn_s[d+64] * sn;
        ok =  kn * cs + kn_s[d+64] * sn;
    } else {
        oq = -qn_s[d-64] * sn + qn * cs;
        ok = -kn_s[d-64] * sn + kn * cs;
    }
    float l0 = lambdas[0], l1 = lambdas[1];
    float vm = l0 * vn + l1 * ve[(size_t)t * DIM + h * HDIM + d];

    size_t oidx = ((size_t)h * T_LEN + t) * HDIM + d;
    float oqs = oq * ATTN_SCALE;
    __nv_bfloat16 qhh = __float2bfloat16(oqs);
    __nv_bfloat16 khh = __float2bfloat16(ok);
    __nv_bfloat16 vhh = __float2bfloat16(vm);
    Qh[oidx] = qhh; Ql[oidx] = __float2bfloat16(oqs - __bfloat162float(qhh));
    Kh[oidx] = khh; Kl[oidx] = __float2bfloat16(ok - __bfloat162float(khh));
    Vh[oidx] = vhh; Vl[oidx] = __float2bfloat16(vm - __bfloat162float(vhh));
}

// ---------------- bf16x3 HMMA causal flash attention ----------------
#define AT_ROWB 272
#define QS_HI 0
#define QS_LO 34816
#define KV_BASE 69632
#define ST_KHI 0
#define ST_KLO 17408
#define ST_VHI 34816
#define ST_VLO 52224
#define ST_BYTES 69632
#define ATTN_SMEM (KV_BASE + 2 * ST_BYTES)

__global__ __launch_bounds__(256, 1) void attn_mma(
    const __nv_bfloat16* __restrict__ Qh, const __nv_bfloat16* __restrict__ Ql,
    const __nv_bfloat16* __restrict__ Kh, const __nv_bfloat16* __restrict__ Kl,
    const __nv_bfloat16* __restrict__ Vh, const __nv_bfloat16* __restrict__ Vl,
    __nv_bfloat16* __restrict__ Yh, uint8_t* __restrict__ Y8)
{
    extern __shared__ char smc[];
    uint32_t sb = smem_to_u32(smc);
    int tid = threadIdx.x, w = tid >> 5, lane = tid & 31;
    int qt = 15 - (int)blockIdx.x;
    int h = blockIdx.y;
    int q0 = qt * 128, nkt = 2 * qt + 2;
    int g = lane >> 2;
    size_t hb = (size_t)h * T_LEN * HDIM;

    {
        const __nv_bfloat16* qsrc = Qh + hb + (size_t)q0 * HDIM;
        const __nv_bfloat16* lsrc = Ql + hb + (size_t)q0 * HDIM;
        #pragma unroll
        for (int rep = 0; rep < 8; rep++) {
            int i = tid + rep * 256;
            int row = i >> 4, ch = i & 15;
            uint32_t d = (uint32_t)(row * AT_ROWB + ch * 16);
            cp16(sb + QS_HI + d, qsrc + row * HDIM + ch * 8);
            cp16(sb + QS_LO + d, lsrc + row * HDIM + ch * 8);
        }
    }
    auto fillKV = [&](int s, int kt) {
        uint32_t b = sb + KV_BASE + s * ST_BYTES;
        size_t base = hb + (size_t)kt * 64 * HDIM;
        #pragma unroll
        for (int rep = 0; rep < 4; rep++) {
            int i = tid + rep * 256;
            int row = i >> 4, ch = i & 15;
            uint32_t d = (uint32_t)(row * AT_ROWB + ch * 16);
            size_t so = base + row * HDIM + ch * 8;
            cp16(b + ST_KHI + d, Kh + so);
            cp16(b + ST_KLO + d, Kl + so);
            cp16(b + ST_VHI + d, Vh + so);
            cp16(b + ST_VLO + d, Vl + so);
        }
    };
    fillKV(0, 0);
    asm volatile("cp.async.commit_group;" ::: "memory");

    float o[16][4];
    #pragma unroll
    for (int jn = 0; jn < 16; jn++)
        #pragma unroll
        for (int u = 0; u < 4; u++) o[jn][u] = 0.0f;
    float m0 = -1e30f, m1 = -1e30f, l0 = 0.0f, l1 = 0.0f;

    for (int kt = 0; kt < nkt; kt++) {
        asm volatile("cp.async.wait_group 0;" ::: "memory");
        __syncthreads();
        if (kt + 1 < nkt) {
            fillKV((kt + 1) & 1, kt + 1);
            asm volatile("cp.async.commit_group;" ::: "memory");
        }
        if (kt * 64 > q0 + w * 16 + 15) continue;
        uint32_t kvs = sb + KV_BASE + (kt & 1) * ST_BYTES;

        float c[8][4];
        #pragma unroll
        for (int jn = 0; jn < 8; jn++)
            #pragma unroll
            for (int u = 0; u < 4; u++) c[jn][u] = 0.0f;

        {
            uint32_t qh[4], ql_[4], bh[2], bl[2];
            #pragma unroll 2
            for (int ks = 0; ks < 8; ks++) {
                uint32_t qa = sb + (uint32_t)((w * 16 + (lane & 15)) * AT_ROWB + ks * 32 + (lane >> 4) * 16);
                ldsm4(qh, qa + QS_HI);
                ldsm4(ql_, qa + QS_LO);
                #pragma unroll
                for (int jn = 0; jn < 8; jn++) {
                    uint32_t ka = kvs + (uint32_t)((jn * 8 + (lane & 7)) * AT_ROWB + ks * 32 + ((lane >> 3) & 1) * 16);
                    ldsm2(bh, ka + ST_KHI);
                    ldsm2(bl, ka + ST_KLO);
                    mma16816(c[jn], qh, bh);
                    mma16816(c[jn], qh, bl);
                    mma16816(c[jn], ql_, bh);
                }
            }
        }

        if (kt * 64 + 63 > q0 + w * 16) {
            int r0 = q0 + w * 16 + g;
            #pragma unroll
            for (int jn = 0; jn < 8; jn++) {
                int cb = kt * 64 + jn * 8 + (lane & 3) * 2;
                if (cb     > r0)     c[jn][0] = -1e30f;
                if (cb + 1 > r0)     c[jn][1] = -1e30f;
                if (cb     > r0 + 8) c[jn][2] = -1e30f;
                if (cb + 1 > r0 + 8) c[jn][3] = -1e30f;
            }
        }

        float mx0 = -1e30f, mx1 = -1e30f;
        #pragma unroll
        for (int jn = 0; jn < 8; jn++) {
            mx0 = fmaxf(mx0, fmaxf(c[jn][0], c[jn][1]));
            mx1 = fmaxf(mx1, fmaxf(c[jn][2], c[jn][3]));
        }
        mx0 = fmaxf(mx0, __shfl_xor_sync(0xffffffffu, mx0, 1));
        mx0 = fmaxf(mx0, __shfl_xor_sync(0xffffffffu, mx0, 2));
        mx1 = fmaxf(mx1, __shfl_xor_sync(0xffffffffu, mx1, 1));
        mx1 = fmaxf(mx1, __shfl_xor_sync(0xffffffffu, mx1, 2));
        float mn0 = fmaxf(m0, mx0), mn1 = fmaxf(m1, mx1);
        float a0 = fexp(m0 - mn0), a1 = fexp(m1 - mn1);
        m0 = mn0; m1 = mn1;
        l0 *= a0; l1 *= a1;
        #pragma unroll
        for (int jn = 0; jn < 16; jn++) {
            o[jn][0] *= a0; o[jn][1] *= a0;
            o[jn][2] *= a1; o[jn][3] *= a1;
        }
        float rs0 = 0.0f, rs1 = 0.0f;
        #pragma unroll
        for (int jn = 0; jn < 8; jn++) {
            c[jn][0] = fexp(c[jn][0] - mn0);
            c[jn][1] = fexp(c[jn][1] - mn0);
            c[jn][2] = fexp(c[jn][2] - mn1);
            c[jn][3] = fexp(c[jn][3] - mn1);
            rs0 += c[jn][0] + c[jn][1];
            rs1 += c[jn][2] + c[jn][3];
        }
        rs0 += __shfl_xor_sync(0xffffffffu, rs0, 1);
        rs0 += __shfl_xor_sync(0xffffffffu, rs0, 2);
        rs1 += __shfl_xor_sync(0xffffffffu, rs1, 1);
        rs1 += __shfl_xor_sync(0xffffffffu, rs1, 2);
        l0 += rs0; l1 += rs1;

        #pragma unroll
        for (int kk = 0; kk < 4; kk++) {
            uint32_t ah[4], al[4];
            #pragma unroll
            for (int half = 0; half < 2; half++) {
                int t2 = 2 * kk + half;
                __nv_bfloat162 h01 = __floats2bfloat162_rn(c[t2][0], c[t2][1]);
                __nv_bfloat162 h23 = __floats2bfloat162_rn(c[t2][2], c[t2][3]);
                __nv_bfloat162 L01 = __floats2bfloat162_rn(
                    c[t2][0] - __bfloat162float(h01.x), c[t2][1] - __bfloat162float(h01.y));
                __nv_bfloat162 L23 = __floats2bfloat162_rn(
                    c[t2][2] - __bfloat162float(h23.x), c[t2][3] - __bfloat162float(h23.y));
                ah[half * 2 + 0] = *(uint32_t*)&h01;
                ah[half * 2 + 1] = *(uint32_t*)&h23;
                al[half * 2 + 0] = *(uint32_t*)&L01;
                al[half * 2 + 1] = *(uint32_t*)&L23;
            }
            uint32_t af_h[4] = {ah[0], ah[1], ah[2], ah[3]};
            uint32_t af_l[4] = {al[0], al[1], al[2], al[3]};
            uint32_t bh[2], bl[2];
            #pragma unroll
            for (int jn = 0; jn < 16; jn++) {
                uint32_t va = kvs + (uint32_t)((kk * 16 + (lane & 15)) * AT_ROWB + jn * 16);
                ldsm2t(bh, va + ST_VHI);
                ldsm2t(bl, va + ST_VLO);
                mma16816(o[jn], af_h, bh);
                mma16816(o[jn], af_h, bl);
                mma16816(o[jn], af_l, bh);
            }
        }
    }

    // ---- epilogue: y -> bf16 hi + fp8 (a-format: [hi|lo], scales 1 / 2^9) ----
    float inv0 = 1.0f / l0, inv1 = 1.0f / l1;
    int r0 = q0 + w * 16 + g;
    #pragma unroll
    for (int jn = 0; jn < 16; jn++) {
        int col = h * HDIM + jn * 8 + (lane & 3) * 2;
        float v0 = o[jn][0] * inv0, v1 = o[jn][1] * inv0;
        float v2 = o[jn][2] * inv1, v3 = o[jn][3] * inv1;
        __nv_bfloat162 h01 = __floats2bfloat162_rn(v0, v1);
        __nv_bfloat162 h23 = __floats2bfloat162_rn(v2, v3);
        *(__nv_bfloat162*)(Yh + (size_t)r0 * DIM + col) = h01;
        *(__nv_bfloat162*)(Yh + (size_t)(r0 + 8) * DIM + col) = h23;

        float lo0 = (v0 - __bfloat162float(h01.x)) * 512.0f;
        float lo1 = (v1 - __bfloat162float(h01.y)) * 512.0f;
        float lo2 = (v2 - __bfloat162float(h23.x)) * 512.0f;
        float lo3 = (v3 - __bfloat162float(h23.y)) * 512.0f;
        uint16_t p8h0 = (uint16_t)__nv_cvt_float2_to_fp8x2(make_float2(v0, v1), __NV_SATFINITE, __NV_E4M3);
        uint16_t p8l0 = (uint16_t)__nv_cvt_float2_to_fp8x2(make_float2(lo0, lo1), __NV_SATFINITE, __NV_E4M3);
        uint16_t p8h1 = (uint16_t)__nv_cvt_float2_to_fp8x2(make_float2(v2, v3), __NV_SATFINITE, __NV_E4M3);
        uint16_t p8l1 = (uint16_t)__nv_cvt_float2_to_fp8x2(make_float2(lo2, lo3), __NV_SATFINITE, __NV_E4M3);
        size_t b0 = (size_t)r0 * (2 * DIM) + (col >> 5) * 64 + (col & 31);
        size_t b1 = (size_t)(r0 + 8) * (2 * DIM) + (col >> 5) * 64 + (col & 31);
        *(uint16_t*)(Y8 + b0)      = p8h0;
        *(uint16_t*)(Y8 + b0 + 32) = p8l0;
        *(uint16_t*)(Y8 + b1)      = p8h1;
        *(uint16_t*)(Y8 + b1 + 32) = p8l1;
    }
}

// ---------------- launch ----------------
extern "C" void kernel_launch(void* const* d_in, const int* in_sizes, int n_in,
                              void* d_out, int out_size)
{
    const float* x       = (const float*)d_in[0];
    const float* w       = (const float*)d_in[1];
    const float* ve      = (const float*)d_in[2];
    const float* lambdas = (const float*)d_in[3];
    float* out = (float*)d_out;

    float *p_qkv;
    __nv_bfloat16 *p_whi, *p_xhi, *p_yhi;
    uint8_t *p_w8, *p_x8, *p_y8;
    __nv_bfloat16 *p_qh, *p_ql, *p_kh, *p_kl, *p_vh, *p_vl;
    cudaGetSymbolAddress((void**)&p_qkv, g_qkv);
    cudaGetSymbolAddress((void**)&p_whi, g_whi);
    cudaGetSymbolAddress((void**)&p_xhi, g_xhi);
    cudaGetSymbolAddress((void**)&p_yhi, g_yhi);
    cudaGetSymbolAddress((void**)&p_w8, g_w8);
    cudaGetSymbolAddress((void**)&p_x8, g_x8);
    cudaGetSymbolAddress((void**)&p_y8, g_y8);
    cudaGetSymbolAddress((void**)&p_qh, g_qh);
    cudaGetSymbolAddress((void**)&p_ql, g_ql);
    cudaGetSymbolAddress((void**)&p_kh, g_kh);
    cudaGetSymbolAddress((void**)&p_kl, g_kl);
    cudaGetSymbolAddress((void**)&p_vh, g_vh);
    cudaGetSymbolAddress((void**)&p_vl, g_vl);

    cudaFuncSetAttribute(gemm_hif8, cudaFuncAttributeMaxDynamicSharedMemorySize, GEMM_SMEM);
    cudaFuncSetAttribute(attn_mma, cudaFuncAttributeMaxDynamicSharedMemorySize, ATTN_SMEM);

    // splits: A-type (x): scales (1, 2^9), [hi|lo]; B-type (w): scales (2^5, 2^14), [lo|hi]
    split_kernel<<<(4*DIM*(DIM/32))/256, 256>>>(w, p_whi, p_w8, DIM, 32.0f, 16384.0f, 1);
    split_kernel<<<(T_LEN*(DIM/32))/256, 256>>>(x, p_xhi, p_x8, DIM, 1.0f, 512.0f, 0);

    gemm_hif8<<<dim3(3*DIM/128, T_LEN/128), 256, GEMM_SMEM>>>(
        p_xhi, p_x8, p_whi, p_w8, p_qkv, T_LEN, 3*DIM, DIM);

    fuse_kernel<<<dim3(T_LEN, NHEAD), 128>>>(p_qkv, ve, lambdas,
        p_qh, p_ql, p_kh, p_kl, p_vh, p_vl);

    attn_mma<<<dim3(16, NHEAD), 256, ATTN_SMEM>>>(
        p_qh, p_ql, p_kh, p_kl, p_vh, p_vl, p_yhi, p_y8);

    gemm_hif8<<<dim3(DIM/128, T_LEN/128), 256, GEMM_SMEM>>>(
        p_yhi, p_y8, p_whi + (size_t)3*DIM*DIM, p_w8 + (size_t)3*DIM*2*DIM, out, T_LEN, DIM, DIM);
}